// round 3
// baseline (speedup 1.0000x reference)
#include <cuda_runtime.h>
#include <math.h>

// Problem constants
#define NTOKS 4096   // B*T
#define DIMV  512
#define QDV   2048   // 2*H*DH
#define HV    8
#define DHV   128
#define NKV   256
#define KKV   16

// Scratch (allocation-free rule: __device__ globals)
__device__ __align__(16) float g_q[NTOKS * QDV];              // 32MB: projected (then LN'd) q
__device__ __align__(16) float g_top_s[NTOKS * HV * 2 * KKV]; // top-16 scores per (t,h,p)
__device__ __align__(16) int   g_top_i[NTOKS * HV * 2 * KKV]; // top-16 indices per (t,h,p)
__device__ __align__(16) float g_attn[NTOKS * HV * KKV];      // softmax weights
__device__ __align__(16) int   g_vidx[NTOKS * HV * KKV];      // value row indices

// ---------------------------------------------------------------------------
// K1: q = x @ Wq^T   (M=4096, N=2048, K=512), fp32 tiled SGEMM 128x128x8
// ---------------------------------------------------------------------------
__global__ __launch_bounds__(256) void k1_gemm(const float* __restrict__ X,
                                               const float* __restrict__ W)
{
    __shared__ float As[8][132];  // padded to kill store conflicts
    __shared__ float Bs[8][132];

    const int tid = threadIdx.x;
    const int tx = tid & 15;      // n-group
    const int ty = tid >> 4;      // m-group
    const int m0 = blockIdx.x * 128;
    const int n0 = blockIdx.y * 128;

    const int lr = tid >> 1;          // 0..127 row to stage
    const int lc = (tid & 1) << 2;    // 0 or 4 (k offset)
    const float* Ap = X + (size_t)(m0 + lr) * DIMV + lc;
    const float* Bp = W + (size_t)(n0 + lr) * DIMV + lc;

    float acc[8][8];
#pragma unroll
    for (int i = 0; i < 8; i++)
#pragma unroll
        for (int j = 0; j < 8; j++) acc[i][j] = 0.f;

    for (int kt = 0; kt < DIMV; kt += 8) {
        float4 a4 = *(const float4*)(Ap + kt);
        float4 b4 = *(const float4*)(Bp + kt);
        As[lc + 0][lr] = a4.x; As[lc + 1][lr] = a4.y;
        As[lc + 2][lr] = a4.z; As[lc + 3][lr] = a4.w;
        Bs[lc + 0][lr] = b4.x; Bs[lc + 1][lr] = b4.y;
        Bs[lc + 2][lr] = b4.z; Bs[lc + 3][lr] = b4.w;
        __syncthreads();
#pragma unroll
        for (int k = 0; k < 8; k++) {
            float a[8], b[8];
#pragma unroll
            for (int i = 0; i < 8; i++) a[i] = As[k][ty + 16 * i];
#pragma unroll
            for (int j = 0; j < 8; j++) b[j] = Bs[k][tx + 16 * j];
#pragma unroll
            for (int i = 0; i < 8; i++)
#pragma unroll
                for (int j = 0; j < 8; j++)
                    acc[i][j] = fmaf(a[i], b[j], acc[i][j]);
        }
        __syncthreads();
    }

#pragma unroll
    for (int i = 0; i < 8; i++) {
        int m = m0 + ty + 16 * i;
#pragma unroll
        for (int j = 0; j < 8; j++) {
            int n = n0 + tx + 16 * j;
            g_q[(size_t)m * QDV + n] = acc[i][j];
        }
    }
}

// ---------------------------------------------------------------------------
// K2: LayerNorm over each 128-elem subrow of g_q (in place). Warp per row.
// ---------------------------------------------------------------------------
__global__ __launch_bounds__(256) void k2_ln(const float* __restrict__ gamma,
                                             const float* __restrict__ beta)
{
    int gw = (int)((blockIdx.x * blockDim.x + threadIdx.x) >> 5);  // 0..65535
    int lane = threadIdx.x & 31;
    float* row = g_q + (size_t)gw * DHV;

    float4 v = *(float4*)(row + lane * 4);
    float s = v.x + v.y + v.z + v.w;
#pragma unroll
    for (int o = 16; o; o >>= 1) s += __shfl_xor_sync(0xffffffffu, s, o);
    float mu = s * (1.0f / 128.0f);

    float dx = v.x - mu, dy = v.y - mu, dz = v.z - mu, dw = v.w - mu;
    float ss = dx * dx + dy * dy + dz * dz + dw * dw;
#pragma unroll
    for (int o = 16; o; o >>= 1) ss += __shfl_xor_sync(0xffffffffu, ss, o);
    float inv = rsqrtf(ss * (1.0f / 128.0f) + 1e-5f);

    float4 g4 = *(const float4*)(gamma + lane * 4);
    float4 b4 = *(const float4*)(beta + lane * 4);
    v.x = dx * inv * g4.x + b4.x;
    v.y = dy * inv * g4.y + b4.y;
    v.z = dz * inv * g4.z + b4.z;
    v.w = dw * inv * g4.w + b4.w;
    *(float4*)(row + lane * 4) = v;
}

// ---------------------------------------------------------------------------
// K3: dots = qn . keys per (t,h,p) over 256 keys of dim 128, fused top-16.
// Block: 256 threads, 32 tokens x one (h,p). Thread (tx,ty): tokens ty+8i,
// keys tx+32j -> each warp (fixed ty) owns ALL 256 scores of its 4 tokens,
// so top-16 runs on registers with warp shuffles. Tie-break: lower index.
// ---------------------------------------------------------------------------
__global__ __launch_bounds__(256) void k3_dots_topk(const float* __restrict__ keys)
{
    __shared__ float qs[32][33];   // [token][k], padded
    __shared__ float ks[32][256];  // [k][n] transposed

    const int tt = blockIdx.x;          // token tile (0..127)
    const int hp = blockIdx.y;          // 0..15
    const int h = hp >> 1, p = hp & 1;
    const int tid = threadIdx.x;
    const int tx = tid & 31;            // n-lane
    const int ty = tid >> 5;            // token-group (warp id)
    const int t0 = tt * 32;

    const float* qbase = g_q + (size_t)(p * HV + h) * DHV;
    const float* kbase = keys + (size_t)h * (NKV * 2 * DHV) + (size_t)p * DHV;

    float acc[4][8];
#pragma unroll
    for (int i = 0; i < 4; i++)
#pragma unroll
        for (int j = 0; j < 8; j++) acc[i][j] = 0.f;

    const int tl = tid >> 3;            // token row for q staging
    const int kc = (tid & 7) << 2;      // k offset for q staging

    for (int kt = 0; kt < DHV; kt += 32) {
        // stage q tile (32 tokens x 32 k)
        float4 q4 = *(const float4*)(qbase + (size_t)(t0 + tl) * QDV + kt + kc);
        qs[tl][kc + 0] = q4.x; qs[tl][kc + 1] = q4.y;
        qs[tl][kc + 2] = q4.z; qs[tl][kc + 3] = q4.w;
        // stage keys tile transposed: thread = key row n=tid, 32 k values
        const float* kr = kbase + (size_t)tid * (2 * DHV) + kt;
#pragma unroll
        for (int c = 0; c < 8; c++) {
            float4 k4 = *(const float4*)(kr + c * 4);
            ks[c * 4 + 0][tid] = k4.x; ks[c * 4 + 1][tid] = k4.y;
            ks[c * 4 + 2][tid] = k4.z; ks[c * 4 + 3][tid] = k4.w;
        }
        __syncthreads();
#pragma unroll
        for (int k = 0; k < 32; k++) {
            float qv[4], kv[8];
#pragma unroll
            for (int i = 0; i < 4; i++) qv[i] = qs[ty + 8 * i][k];
#pragma unroll
            for (int j = 0; j < 8; j++) kv[j] = ks[k][tx + 32 * j];
#pragma unroll
            for (int i = 0; i < 4; i++)
#pragma unroll
                for (int j = 0; j < 8; j++)
                    acc[i][j] = fmaf(qv[i], kv[j], acc[i][j]);
        }
        __syncthreads();
    }

    // per-warp top-16 over 256 register-resident scores, 4 tokens per warp
#pragma unroll 1
    for (int i = 0; i < 4; i++) {
        float v[8];
#pragma unroll
        for (int j = 0; j < 8; j++) v[j] = acc[i][j];
        int t = t0 + ty + 8 * i;
        float out_s = 0.f; int out_i = 0;
#pragma unroll 1
        for (int s = 0; s < 16; s++) {
            float bv = -INFINITY; int bi = 0x7fffffff;
#pragma unroll
            for (int j = 0; j < 8; j++) {
                int id = tx + 32 * j;
                if (v[j] > bv) { bv = v[j]; bi = id; }
            }
#pragma unroll
            for (int o = 16; o; o >>= 1) {
                float ov = __shfl_xor_sync(0xffffffffu, bv, o);
                int   oi = __shfl_xor_sync(0xffffffffu, bi, o);
                if (ov > bv || (ov == bv && oi < bi)) { bv = ov; bi = oi; }
            }
            if (tx == s) { out_s = bv; out_i = bi; }
            bool own = ((bi & 31) == tx);
            int slot = bi >> 5;
#pragma unroll
            for (int j = 0; j < 8; j++)
                if (own && slot == j) v[j] = -INFINITY;
        }
        if (tx < 16) {
            int o = (((t * HV + h) * 2) + p) * KKV + tx;
            g_top_s[o] = out_s;
            g_top_i[o] = out_i;
        }
    }
}

// ---------------------------------------------------------------------------
// K4: combine: per (t,h) build 16x16 sums sx[i]+sy[j], top-16 of 256,
// softmax, emit attn weights + value indices. Warp per (t,h).
// ---------------------------------------------------------------------------
__global__ __launch_bounds__(256) void k4_combine()
{
    __shared__ float ss[8][32];
    __shared__ int   si[8][32];
    const int tid = threadIdx.x;
    const int lane = tid & 31;
    const int w = tid >> 5;
    const int gw = blockIdx.x * 8 + w;      // 0..32767
    const int t = gw >> 3, h = gw & 7;
    const int base = ((t * HV + h) * 2) * KKV;  // [p0 k0..15 | p1 k0..15]

    ss[w][lane] = g_top_s[base + lane];
    si[w][lane] = g_top_i[base + lane];
    __syncwarp();

    float v[8];
#pragma unroll
    for (int j = 0; j < 8; j++) {
        int cc = lane + 32 * j;
        v[j] = ss[w][cc >> 4] + ss[w][16 + (cc & 15)];
    }

    float out_s = 0.f; int out_c = 0;
#pragma unroll 1
    for (int s = 0; s < 16; s++) {
        float bv = -INFINITY; int bi = 0x7fffffff;
#pragma unroll
        for (int j = 0; j < 8; j++) {
            int cc = lane + 32 * j;
            if (v[j] > bv) { bv = v[j]; bi = cc; }
        }
#pragma unroll
        for (int o = 16; o; o >>= 1) {
            float ov = __shfl_xor_sync(0xffffffffu, bv, o);
            int   oi = __shfl_xor_sync(0xffffffffu, bi, o);
            if (ov > bv || (ov == bv && oi < bi)) { bv = ov; bi = oi; }
        }
        if (lane == s) { out_s = bv; out_c = bi; }
        bool own = ((bi & 31) == lane);
        int slot = bi >> 5;
#pragma unroll
        for (int j = 0; j < 8; j++)
            if (own && slot == j) v[j] = -INFINITY;
    }

    // softmax over the 16 selected (lane 0 holds the max — sorted descending)
    float m = __shfl_sync(0xffffffffu, out_s, 0);
    float e = (lane < 16) ? expf(out_s - m) : 0.f;
    float sum = e;
#pragma unroll
    for (int o = 16; o; o >>= 1) sum += __shfl_xor_sync(0xffffffffu, sum, o);

    if (lane < 16) {
        int cc = out_c;
        int vidx = si[w][cc >> 4] * NKV + si[w][16 + (cc & 15)];
        int o = (t * HV + h) * KKV + lane;
        g_attn[o] = e / sum;
        g_vidx[o] = vidx;
    }
}

// ---------------------------------------------------------------------------
// K5: out[t,:] = sum_{m<128} attn[t,m] * values[vidx[t,m], :]. Block per token,
// 128 threads, float4 per thread over DIM=512.
// ---------------------------------------------------------------------------
__global__ __launch_bounds__(128) void k5_out(const float* __restrict__ values,
                                              float* __restrict__ out)
{
    __shared__ float sa[128];
    __shared__ int   sv[128];
    const int t = blockIdx.x;
    const int tid = threadIdx.x;
    sa[tid] = g_attn[(size_t)t * 128 + tid];
    sv[tid] = g_vidx[(size_t)t * 128 + tid];
    __syncthreads();

    const float4* V = (const float4*)values;
    float4 acc = make_float4(0.f, 0.f, 0.f, 0.f);
#pragma unroll 4
    for (int m = 0; m < 128; m++) {
        float a = sa[m];
        float4 vv = V[(size_t)sv[m] * 128 + tid];
        acc.x = fmaf(a, vv.x, acc.x);
        acc.y = fmaf(a, vv.y, acc.y);
        acc.z = fmaf(a, vv.z, acc.z);
        acc.w = fmaf(a, vv.w, acc.w);
    }
    ((float4*)out)[(size_t)t * 128 + tid] = acc;
}

// ---------------------------------------------------------------------------
extern "C" void kernel_launch(void* const* d_in, const int* in_sizes, int n_in,
                              void* d_out, int out_size)
{
    const float* x      = (const float*)d_in[0];  // (4,1024,512)
    const float* Wq     = (const float*)d_in[1];  // (2048,512)
    const float* ln_g   = (const float*)d_in[2];  // (128,)
    const float* ln_b   = (const float*)d_in[3];  // (128,)
    const float* keys   = (const float*)d_in[4];  // (8,256,2,128)
    const float* values = (const float*)d_in[5];  // (65536,512)
    float* out = (float*)d_out;                   // (4,1024,512)

    // K1: q projection
    k1_gemm<<<dim3(NTOKS / 128, QDV / 128), 256>>>(x, Wq);
    // K2: layernorm (in place)
    k2_ln<<<(NTOKS * 16) / 8, 256>>>(ln_g, ln_b);
    // K3: dots + per-(t,h,p) top-16
    k3_dots_topk<<<dim3(NTOKS / 32, 16), 256>>>(keys);
    // K4: combine + softmax
    k4_combine<<<NTOKS * HV / 8, 256>>>();
    // K5: weighted gather
    k5_out<<<NTOKS, 128>>>(values, out);
}

// round 4
// speedup vs baseline: 1.0030x; 1.0030x over previous
#include <cuda_runtime.h>
#include <math.h>

// Problem constants
#define NTOKS 4096   // B*T
#define DIMV  512
#define QDV   2048   // 2*H*DH
#define HV    8
#define DHV   128
#define NKV   256
#define KKV   16

// Scratch (allocation-free rule: __device__ globals)
__device__ __align__(16) float g_q[NTOKS * QDV];              // 32MB: projected (then LN'd) q
__device__ __align__(16) float g_top_s[NTOKS * HV * 2 * KKV]; // top-16 scores per (t,h,p)
__device__ __align__(16) int   g_top_i[NTOKS * HV * 2 * KKV]; // top-16 indices per (t,h,p)
__device__ __align__(16) float g_attn[NTOKS * HV * KKV];      // softmax weights
__device__ __align__(16) int   g_vidx[NTOKS * HV * KKV];      // value row indices

// ---------------------------------------------------------------------------
// K1: q = x @ Wq^T   (M=4096, N=2048, K=512), fp32 tiled SGEMM 128x128x8
// ---------------------------------------------------------------------------
__global__ __launch_bounds__(256) void k1_gemm(const float* __restrict__ X,
                                               const float* __restrict__ W)
{
    __shared__ float As[8][132];  // padded to kill store conflicts
    __shared__ float Bs[8][132];

    const int tid = threadIdx.x;
    const int tx = tid & 15;      // n-group
    const int ty = tid >> 4;      // m-group
    const int m0 = blockIdx.x * 128;
    const int n0 = blockIdx.y * 128;

    const int lr = tid >> 1;          // 0..127 row to stage
    const int lc = (tid & 1) << 2;    // 0 or 4 (k offset)
    const float* Ap = X + (size_t)(m0 + lr) * DIMV + lc;
    const float* Bp = W + (size_t)(n0 + lr) * DIMV + lc;

    float acc[8][8];
#pragma unroll
    for (int i = 0; i < 8; i++)
#pragma unroll
        for (int j = 0; j < 8; j++) acc[i][j] = 0.f;

    for (int kt = 0; kt < DIMV; kt += 8) {
        float4 a4 = *(const float4*)(Ap + kt);
        float4 b4 = *(const float4*)(Bp + kt);
        As[lc + 0][lr] = a4.x; As[lc + 1][lr] = a4.y;
        As[lc + 2][lr] = a4.z; As[lc + 3][lr] = a4.w;
        Bs[lc + 0][lr] = b4.x; Bs[lc + 1][lr] = b4.y;
        Bs[lc + 2][lr] = b4.z; Bs[lc + 3][lr] = b4.w;
        __syncthreads();
#pragma unroll
        for (int k = 0; k < 8; k++) {
            float a[8], b[8];
#pragma unroll
            for (int i = 0; i < 8; i++) a[i] = As[k][ty + 16 * i];
#pragma unroll
            for (int j = 0; j < 8; j++) b[j] = Bs[k][tx + 16 * j];
#pragma unroll
            for (int i = 0; i < 8; i++)
#pragma unroll
                for (int j = 0; j < 8; j++)
                    acc[i][j] = fmaf(a[i], b[j], acc[i][j]);
        }
        __syncthreads();
    }

#pragma unroll
    for (int i = 0; i < 8; i++) {
        int m = m0 + ty + 16 * i;
#pragma unroll
        for (int j = 0; j < 8; j++) {
            int n = n0 + tx + 16 * j;
            g_q[(size_t)m * QDV + n] = acc[i][j];
        }
    }
}

// ---------------------------------------------------------------------------
// K2: LayerNorm over each 128-elem subrow of g_q (in place). Warp per row.
// ---------------------------------------------------------------------------
__global__ __launch_bounds__(256) void k2_ln(const float* __restrict__ gamma,
                                             const float* __restrict__ beta)
{
    int gw = (int)((blockIdx.x * blockDim.x + threadIdx.x) >> 5);  // 0..65535
    int lane = threadIdx.x & 31;
    float* row = g_q + (size_t)gw * DHV;

    float4 v = *(float4*)(row + lane * 4);
    float s = v.x + v.y + v.z + v.w;
#pragma unroll
    for (int o = 16; o; o >>= 1) s += __shfl_xor_sync(0xffffffffu, s, o);
    float mu = s * (1.0f / 128.0f);

    float dx = v.x - mu, dy = v.y - mu, dz = v.z - mu, dw = v.w - mu;
    float ss = dx * dx + dy * dy + dz * dz + dw * dw;
#pragma unroll
    for (int o = 16; o; o >>= 1) ss += __shfl_xor_sync(0xffffffffu, ss, o);
    float inv = rsqrtf(ss * (1.0f / 128.0f) + 1e-5f);

    float4 g4 = *(const float4*)(gamma + lane * 4);
    float4 b4 = *(const float4*)(beta + lane * 4);
    v.x = dx * inv * g4.x + b4.x;
    v.y = dy * inv * g4.y + b4.y;
    v.z = dz * inv * g4.z + b4.z;
    v.w = dw * inv * g4.w + b4.w;
    *(float4*)(row + lane * 4) = v;
}

// ---------------------------------------------------------------------------
// K3: dots = qn . keys per (t,h,p) over 256 keys of dim 128, fused top-16.
// Block: 256 threads, 32 tokens x one (h,p). Thread (tx,ty): tokens ty+8i,
// keys tx+32j -> each warp (fixed ty) owns ALL 256 scores of its 4 tokens,
// so top-16 runs on registers with warp shuffles. Tie-break: lower index.
// ---------------------------------------------------------------------------
__global__ __launch_bounds__(256) void k3_dots_topk(const float* __restrict__ keys)
{
    __shared__ float qs[32][33];   // [token][k], padded
    __shared__ float ks[32][256];  // [k][n] transposed

    const int tt = blockIdx.x;          // token tile (0..127)
    const int hp = blockIdx.y;          // 0..15
    const int h = hp >> 1, p = hp & 1;
    const int tid = threadIdx.x;
    const int tx = tid & 31;            // n-lane
    const int ty = tid >> 5;            // token-group (warp id)
    const int t0 = tt * 32;

    const float* qbase = g_q + (size_t)(p * HV + h) * DHV;
    const float* kbase = keys + (size_t)h * (NKV * 2 * DHV) + (size_t)p * DHV;

    float acc[4][8];
#pragma unroll
    for (int i = 0; i < 4; i++)
#pragma unroll
        for (int j = 0; j < 8; j++) acc[i][j] = 0.f;

    const int tl = tid >> 3;            // token row for q staging
    const int kc = (tid & 7) << 2;      // k offset for q staging

    for (int kt = 0; kt < DHV; kt += 32) {
        // stage q tile (32 tokens x 32 k)
        float4 q4 = *(const float4*)(qbase + (size_t)(t0 + tl) * QDV + kt + kc);
        qs[tl][kc + 0] = q4.x; qs[tl][kc + 1] = q4.y;
        qs[tl][kc + 2] = q4.z; qs[tl][kc + 3] = q4.w;
        // stage keys tile transposed: thread = key row n=tid, 32 k values
        const float* kr = kbase + (size_t)tid * (2 * DHV) + kt;
#pragma unroll
        for (int c = 0; c < 8; c++) {
            float4 k4 = *(const float4*)(kr + c * 4);
            ks[c * 4 + 0][tid] = k4.x; ks[c * 4 + 1][tid] = k4.y;
            ks[c * 4 + 2][tid] = k4.z; ks[c * 4 + 3][tid] = k4.w;
        }
        __syncthreads();
#pragma unroll
        for (int k = 0; k < 32; k++) {
            float qv[4], kv[8];
#pragma unroll
            for (int i = 0; i < 4; i++) qv[i] = qs[ty + 8 * i][k];
#pragma unroll
            for (int j = 0; j < 8; j++) kv[j] = ks[k][tx + 32 * j];
#pragma unroll
            for (int i = 0; i < 4; i++)
#pragma unroll
                for (int j = 0; j < 8; j++)
                    acc[i][j] = fmaf(qv[i], kv[j], acc[i][j]);
        }
        __syncthreads();
    }

    // per-warp top-16 over 256 register-resident scores, 4 tokens per warp
#pragma unroll 1
    for (int i = 0; i < 4; i++) {
        float v[8];
#pragma unroll
        for (int j = 0; j < 8; j++) v[j] = acc[i][j];
        int t = t0 + ty + 8 * i;
        float out_s = 0.f; int out_i = 0;
#pragma unroll 1
        for (int s = 0; s < 16; s++) {
            float bv = -INFINITY; int bi = 0x7fffffff;
#pragma unroll
            for (int j = 0; j < 8; j++) {
                int id = tx + 32 * j;
                if (v[j] > bv) { bv = v[j]; bi = id; }
            }
#pragma unroll
            for (int o = 16; o; o >>= 1) {
                float ov = __shfl_xor_sync(0xffffffffu, bv, o);
                int   oi = __shfl_xor_sync(0xffffffffu, bi, o);
                if (ov > bv || (ov == bv && oi < bi)) { bv = ov; bi = oi; }
            }
            if (tx == s) { out_s = bv; out_i = bi; }
            bool own = ((bi & 31) == tx);
            int slot = bi >> 5;
#pragma unroll
            for (int j = 0; j < 8; j++)
                if (own && slot == j) v[j] = -INFINITY;
        }
        if (tx < 16) {
            int o = (((t * HV + h) * 2) + p) * KKV + tx;
            g_top_s[o] = out_s;
            g_top_i[o] = out_i;
        }
    }
}

// ---------------------------------------------------------------------------
// K4: combine: per (t,h) build 16x16 sums sx[i]+sy[j], top-16 of 256,
// softmax, emit attn weights + value indices. Warp per (t,h).
// ---------------------------------------------------------------------------
__global__ __launch_bounds__(256) void k4_combine()
{
    __shared__ float ss[8][32];
    __shared__ int   si[8][32];
    const int tid = threadIdx.x;
    const int lane = tid & 31;
    const int w = tid >> 5;
    const int gw = blockIdx.x * 8 + w;      // 0..32767
    const int t = gw >> 3, h = gw & 7;
    const int base = ((t * HV + h) * 2) * KKV;  // [p0 k0..15 | p1 k0..15]

    ss[w][lane] = g_top_s[base + lane];
    si[w][lane] = g_top_i[base + lane];
    __syncwarp();

    float v[8];
#pragma unroll
    for (int j = 0; j < 8; j++) {
        int cc = lane + 32 * j;
        v[j] = ss[w][cc >> 4] + ss[w][16 + (cc & 15)];
    }

    float out_s = 0.f; int out_c = 0;
#pragma unroll 1
    for (int s = 0; s < 16; s++) {
        float bv = -INFINITY; int bi = 0x7fffffff;
#pragma unroll
        for (int j = 0; j < 8; j++) {
            int cc = lane + 32 * j;
            if (v[j] > bv) { bv = v[j]; bi = cc; }
        }
#pragma unroll
        for (int o = 16; o; o >>= 1) {
            float ov = __shfl_xor_sync(0xffffffffu, bv, o);
            int   oi = __shfl_xor_sync(0xffffffffu, bi, o);
            if (ov > bv || (ov == bv && oi < bi)) { bv = ov; bi = oi; }
        }
        if (lane == s) { out_s = bv; out_c = bi; }
        bool own = ((bi & 31) == lane);
        int slot = bi >> 5;
#pragma unroll
        for (int j = 0; j < 8; j++)
            if (own && slot == j) v[j] = -INFINITY;
    }

    // softmax over the 16 selected (lane 0 holds the max — sorted descending)
    float m = __shfl_sync(0xffffffffu, out_s, 0);
    float e = (lane < 16) ? expf(out_s - m) : 0.f;
    float sum = e;
#pragma unroll
    for (int o = 16; o; o >>= 1) sum += __shfl_xor_sync(0xffffffffu, sum, o);

    if (lane < 16) {
        int cc = out_c;
        int vidx = si[w][cc >> 4] * NKV + si[w][16 + (cc & 15)];
        int o = (t * HV + h) * KKV + lane;
        g_attn[o] = e / sum;
        g_vidx[o] = vidx;
    }
}

// ---------------------------------------------------------------------------
// K5: out[t,:] = sum_{m<128} attn[t,m] * values[vidx[t,m], :]. Block per token,
// 128 threads, float4 per thread over DIM=512.
// ---------------------------------------------------------------------------
__global__ __launch_bounds__(128) void k5_out(const float* __restrict__ values,
                                              float* __restrict__ out)
{
    __shared__ float sa[128];
    __shared__ int   sv[128];
    const int t = blockIdx.x;
    const int tid = threadIdx.x;
    sa[tid] = g_attn[(size_t)t * 128 + tid];
    sv[tid] = g_vidx[(size_t)t * 128 + tid];
    __syncthreads();

    const float4* V = (const float4*)values;
    float4 acc = make_float4(0.f, 0.f, 0.f, 0.f);
#pragma unroll 4
    for (int m = 0; m < 128; m++) {
        float a = sa[m];
        float4 vv = V[(size_t)sv[m] * 128 + tid];
        acc.x = fmaf(a, vv.x, acc.x);
        acc.y = fmaf(a, vv.y, acc.y);
        acc.z = fmaf(a, vv.z, acc.z);
        acc.w = fmaf(a, vv.w, acc.w);
    }
    ((float4*)out)[(size_t)t * 128 + tid] = acc;
}

// ---------------------------------------------------------------------------
extern "C" void kernel_launch(void* const* d_in, const int* in_sizes, int n_in,
                              void* d_out, int out_size)
{
    const float* x      = (const float*)d_in[0];  // (4,1024,512)
    const float* Wq     = (const float*)d_in[1];  // (2048,512)
    const float* ln_g   = (const float*)d_in[2];  // (128,)
    const float* ln_b   = (const float*)d_in[3];  // (128,)
    const float* keys   = (const float*)d_in[4];  // (8,256,2,128)
    const float* values = (const float*)d_in[5];  // (65536,512)
    float* out = (float*)d_out;                   // (4,1024,512)

    // K1: q projection
    k1_gemm<<<dim3(NTOKS / 128, QDV / 128), 256>>>(x, Wq);
    // K2: layernorm (in place)
    k2_ln<<<(NTOKS * 16) / 8, 256>>>(ln_g, ln_b);
    // K3: dots + per-(t,h,p) top-16
    k3_dots_topk<<<dim3(NTOKS / 32, 16), 256>>>(keys);
    // K4: combine + softmax
    k4_combine<<<NTOKS * HV / 8, 256>>>();
    // K5: weighted gather
    k5_out<<<NTOKS, 128>>>(values, out);
}

// round 6
// speedup vs baseline: 1.1281x; 1.1246x over previous
#include <cuda_runtime.h>
#include <math.h>

// Problem constants
#define NTOKS 4096   // B*T
#define DIMV  512
#define QDV   2048   // 2*H*DH
#define HV    8
#define DHV   128
#define NKV   256
#define KKV   16

typedef unsigned long long ull;

// packed fp32x2 FMA (sm_103a FFMA2) — bit-exact fp32 per lane, 2x FMA throughput
#define FMA2(d, a, b) \
    asm("fma.rn.f32x2 %0, %1, %2, %0;" : "+l"(d) : "l"(a), "l"(b))
#define PACKDUP(out, x) \
    asm("mov.b64 %0, {%1, %1};" : "=l"(out) : "r"(__float_as_uint(x)))
#define UNPACK2(lo, hi, in) \
    asm("mov.b64 {%0, %1}, %2;" : "=r"(lo), "=r"(hi) : "l"(in))

// Scratch (allocation-free rule: __device__ globals)
__device__ __align__(16) float g_q[NTOKS * QDV];          // projected then LN'd q
__device__ __align__(16) float g_attn[NTOKS * HV * KKV];  // softmax weights
__device__ __align__(16) int   g_vidx[NTOKS * HV * KKV];  // value row indices

// Stage-2 candidate tables: (i,j) with (i+1)(j+1) <= 16 — 50 candidates,
// provably a superset of the top-16 of sx[i]+sy[j] with sx,sy sorted desc
// (exact under the reference's lower-flattened-index tie-break).
__device__ __constant__ int c_ci[64] = {
    0,0,0,0,0,0,0,0,0,0,0,0,0,0,0,0,
    1,1,1,1,1,1,1,1,
    2,2,2,2,2,
    3,3,3,3,
    4,4,4,
    5,5, 6,6, 7,7,
    8,9,10,11,12,13,14,15,
    0,0,0,0,0,0,0,0,0,0,0,0,0,0};
__device__ __constant__ int c_cj[64] = {
    0,1,2,3,4,5,6,7,8,9,10,11,12,13,14,15,
    0,1,2,3,4,5,6,7,
    0,1,2,3,4,
    0,1,2,3,
    0,1,2,
    0,1, 0,1, 0,1,
    0,0,0,0,0,0,0,0,
    0,0,0,0,0,0,0,0,0,0,0,0,0,0};

// ---------------------------------------------------------------------------
// K1: q = x @ Wq^T  (M=4096, N=2048, K=512) with FFMA2 (bit-exact fp32,
// same sequential-k fmaf chain as the round-2 kernel). Raw store to g_q.
// ---------------------------------------------------------------------------
__global__ __launch_bounds__(256) void k1_gemm(const float* __restrict__ X,
                                               const float* __restrict__ W)
{
    __shared__ float As[16][132];  // [k][m]
    __shared__ float Bs[16][132];  // [k][n]

    const int tid = threadIdx.x;
    const int tx = tid & 15;       // n-group
    const int ty = tid >> 4;       // m-group
    const int m0 = blockIdx.x * 128;
    const int n0 = blockIdx.y * 128;

    ull acc[4][8];                 // [row-pair][col]
#pragma unroll
    for (int ip = 0; ip < 4; ip++)
#pragma unroll
        for (int j = 0; j < 8; j++) acc[ip][j] = 0ULL;

    for (int kt = 0; kt < DIMV; kt += 16) {
        // stage 128x16 of A and B (2 float4 per thread each), transposed
#pragma unroll
        for (int q = 0; q < 2; q++) {
            int idx = q * 256 + tid;
            int row = idx >> 2;
            int kc = (idx & 3) << 2;
            float4 a4 = *(const float4*)(X + (size_t)(m0 + row) * DIMV + kt + kc);
            As[kc + 0][row] = a4.x; As[kc + 1][row] = a4.y;
            As[kc + 2][row] = a4.z; As[kc + 3][row] = a4.w;
            float4 b4 = *(const float4*)(W + (size_t)(n0 + row) * DIMV + kt + kc);
            Bs[kc + 0][row] = b4.x; Bs[kc + 1][row] = b4.y;
            Bs[kc + 2][row] = b4.z; Bs[kc + 3][row] = b4.w;
        }
        __syncthreads();
#pragma unroll 4
        for (int k = 0; k < 16; k++) {
            // a: natural fp32 pairs via vector LDS (rows ty*4+{0,1},{2,3}, +64)
            ulonglong2 a01 = *(const ulonglong2*)&As[k][ty * 4];
            ulonglong2 a23 = *(const ulonglong2*)&As[k][64 + ty * 4];
            ull av[4] = {a01.x, a01.y, a23.x, a23.y};
            // b: 8 scalars, duplicated into pairs
            float4 bl = *(const float4*)&Bs[k][tx * 4];
            float4 bh = *(const float4*)&Bs[k][64 + tx * 4];
            ull bd[8];
            PACKDUP(bd[0], bl.x); PACKDUP(bd[1], bl.y);
            PACKDUP(bd[2], bl.z); PACKDUP(bd[3], bl.w);
            PACKDUP(bd[4], bh.x); PACKDUP(bd[5], bh.y);
            PACKDUP(bd[6], bh.z); PACKDUP(bd[7], bh.w);
#pragma unroll
            for (int ip = 0; ip < 4; ip++)
#pragma unroll
                for (int j = 0; j < 8; j++)
                    FMA2(acc[ip][j], av[ip], bd[j]);
        }
        __syncthreads();
    }

    // raw store (LN done by k2, verbatim round-2 kernel, for bit-exactness)
#pragma unroll
    for (int ip = 0; ip < 4; ip++) {
#pragma unroll
        for (int e = 0; e < 2; e++) {
            int row = (ip >> 1) * 64 + ty * 4 + (ip & 1) * 2 + e;  // local m
            float o[8];
#pragma unroll
            for (int j = 0; j < 8; j++) {
                unsigned lo, hi;
                UNPACK2(lo, hi, acc[ip][j]);
                o[j] = __uint_as_float(e ? hi : lo);
            }
            float* dst = g_q + (size_t)(m0 + row) * QDV + n0;
            *(float4*)(dst + tx * 4)      = make_float4(o[0], o[1], o[2], o[3]);
            *(float4*)(dst + 64 + tx * 4) = make_float4(o[4], o[5], o[6], o[7]);
        }
    }
}

// ---------------------------------------------------------------------------
// K2: LayerNorm over each 128-elem subrow of g_q (in place). Warp per row.
// VERBATIM round-2 kernel (bit-exact reduction tree).
// ---------------------------------------------------------------------------
__global__ __launch_bounds__(256) void k2_ln(const float* __restrict__ gamma,
                                             const float* __restrict__ beta)
{
    int gw = (int)((blockIdx.x * blockDim.x + threadIdx.x) >> 5);  // 0..65535
    int lane = threadIdx.x & 31;
    float* row = g_q + (size_t)gw * DHV;

    float4 v = *(float4*)(row + lane * 4);
    float s = v.x + v.y + v.z + v.w;
#pragma unroll
    for (int o = 16; o; o >>= 1) s += __shfl_xor_sync(0xffffffffu, s, o);
    float mu = s * (1.0f / 128.0f);

    float dx = v.x - mu, dy = v.y - mu, dz = v.z - mu, dw = v.w - mu;
    float ss = dx * dx + dy * dy + dz * dz + dw * dw;
#pragma unroll
    for (int o = 16; o; o >>= 1) ss += __shfl_xor_sync(0xffffffffu, ss, o);
    float inv = rsqrtf(ss * (1.0f / 128.0f) + 1e-5f);

    float4 g4 = *(const float4*)(gamma + lane * 4);
    float4 b4 = *(const float4*)(beta + lane * 4);
    v.x = dx * inv * g4.x + b4.x;
    v.y = dy * inv * g4.y + b4.y;
    v.z = dz * inv * g4.z + b4.z;
    v.w = dw * inv * g4.w + b4.w;
    *(float4*)(row + lane * 4) = v;
}

// ---------------------------------------------------------------------------
// K3 (fused K4): per (32-token tile, head h): dots vs 512 keys (both p) with
// FFMA2 (bit-identical k-order), stage-1 top-16 per p in registers, stage-2
// pruned combine (50 cands, exact), softmax, emit attn + value indices.
// ---------------------------------------------------------------------------
__global__ __launch_bounds__(256) void k3_fused(const float* __restrict__ keys)
{
    __shared__ float qs[32][33];   // [token][k]
    __shared__ float ks[32][256];  // [k][key] transposed

    const int tid = threadIdx.x;
    const int tx = tid & 31;
    const int wy = tid >> 5;       // warp id: token group
    const int tt = blockIdx.x;
    const int h = blockIdx.y;
    const int t0 = tt * 32;

    ull acc[2][4][4];              // [p][token][key-pair-quad]
#pragma unroll
    for (int p = 0; p < 2; p++)
#pragma unroll
        for (int i = 0; i < 4; i++)
#pragma unroll
            for (int jq = 0; jq < 4; jq++) acc[p][i][jq] = 0ULL;

    const int tl = tid >> 3;
    const int kc = (tid & 7) << 2;

    for (int p = 0; p < 2; p++) {
        const float* qb = g_q + (size_t)(p * HV + h) * DHV;
        const float* kb = keys + ((size_t)(h * NKV + tid) * 2 + p) * DHV;
        for (int kt = 0; kt < DHV; kt += 32) {
            __syncthreads();
            float4 q4 = *(const float4*)(qb + (size_t)(t0 + tl) * QDV + kt + kc);
            qs[tl][kc + 0] = q4.x; qs[tl][kc + 1] = q4.y;
            qs[tl][kc + 2] = q4.z; qs[tl][kc + 3] = q4.w;
            const float* kr = kb + kt;  // key row n = tid (256 keys)
#pragma unroll
            for (int c = 0; c < 8; c++) {
                float4 k4 = *(const float4*)(kr + c * 4);
                ks[c * 4 + 0][tid] = k4.x; ks[c * 4 + 1][tid] = k4.y;
                ks[c * 4 + 2][tid] = k4.z; ks[c * 4 + 3][tid] = k4.w;
            }
            __syncthreads();
#pragma unroll 4
            for (int k = 0; k < 32; k++) {
                ull kv[4];
#pragma unroll
                for (int jq = 0; jq < 4; jq++)
                    kv[jq] = *(const ull*)&ks[k][64 * jq + 2 * tx];
#pragma unroll
                for (int i = 0; i < 4; i++) {
                    ull qd;
                    PACKDUP(qd, qs[wy + 8 * i][k]);
#pragma unroll
                    for (int jq = 0; jq < 4; jq++)
                        FMA2(acc[p][i][jq], qd, kv[jq]);
                }
            }
        }
    }

    // selection per token
#pragma unroll 1
    for (int i = 0; i < 4; i++) {
        const int t = t0 + wy + 8 * i;
        float s1s[2];
        int s1i[2];
        // stage 1: top-16 of 256 per p (after: lane l<16 holds l-th best)
#pragma unroll 1
        for (int p = 0; p < 2; p++) {
            float v[8];
#pragma unroll
            for (int jq = 0; jq < 4; jq++) {
                unsigned lo, hi;
                UNPACK2(lo, hi, acc[p][i][jq]);
                v[2 * jq + 0] = __uint_as_float(lo);
                v[2 * jq + 1] = __uint_as_float(hi);
            }
            float os = 0.f; int oi = 0;
#pragma unroll 1
            for (int it = 0; it < 16; it++) {
                float bv = -INFINITY; int bi = 0x7fffffff;
#pragma unroll
                for (int s = 0; s < 8; s++) {
                    int n = ((s >> 1) << 6) + 2 * tx + (s & 1);
                    if (v[s] > bv) { bv = v[s]; bi = n; }
                }
#pragma unroll
                for (int o = 16; o; o >>= 1) {
                    float ov = __shfl_xor_sync(0xffffffffu, bv, o);
                    int oi2 = __shfl_xor_sync(0xffffffffu, bi, o);
                    if (ov > bv || (ov == bv && oi2 < bi)) { bv = ov; bi = oi2; }
                }
                if (tx == it) { os = bv; oi = bi; }
                if (((bi >> 1) & 31) == tx) {
                    int sl = ((bi >> 6) << 1) | (bi & 1);
                    v[sl] = -INFINITY;
                }
            }
            s1s[p] = os; s1i[p] = oi;
        }

        // stage 2: top-16 of 50 pruned candidates (lane l: c=l and c=l+32)
        float v2[2]; int cc2[2];
#pragma unroll
        for (int e = 0; e < 2; e++) {
            int c = tx + 32 * e;
            int ii = c_ci[c], jj = c_cj[c];
            float sxv = __shfl_sync(0xffffffffu, s1s[0], ii);
            float syv = __shfl_sync(0xffffffffu, s1s[1], jj);
            v2[e] = (c < 50) ? sxv + syv : -INFINITY;
            cc2[e] = ii * 16 + jj;
        }
        float os = 0.f; int occ = 0;
#pragma unroll 1
        for (int it = 0; it < 16; it++) {
            float bv = -INFINITY; int bcc = 0x7fffffff;
#pragma unroll
            for (int e = 0; e < 2; e++)
                if (v2[e] > bv || (v2[e] == bv && cc2[e] < bcc)) { bv = v2[e]; bcc = cc2[e]; }
#pragma unroll
            for (int o = 16; o; o >>= 1) {
                float ov = __shfl_xor_sync(0xffffffffu, bv, o);
                int oc2 = __shfl_xor_sync(0xffffffffu, bcc, o);
                if (ov > bv || (ov == bv && oc2 < bcc)) { bv = ov; bcc = oc2; }
            }
            if (tx == it) { os = bv; occ = bcc; }
#pragma unroll
            for (int e = 0; e < 2; e++)
                if (cc2[e] == bcc) v2[e] = -INFINITY;
        }

        // softmax over 16 selected (lane 0 = max) + index gather
        float mx = __shfl_sync(0xffffffffu, os, 0);
        float ev = (tx < 16) ? expf(os - mx) : 0.f;
        float sum = ev;
#pragma unroll
        for (int o = 16; o; o >>= 1) sum += __shfl_xor_sync(0xffffffffu, sum, o);
        int ix = __shfl_sync(0xffffffffu, s1i[0], (occ >> 4) & 15);
        int iy = __shfl_sync(0xffffffffu, s1i[1], occ & 15);
        if (tx < 16) {
            int o = (t * HV + h) * KKV + tx;
            g_attn[o] = ev / sum;
            g_vidx[o] = ix * NKV + iy;
        }
    }
}

// ---------------------------------------------------------------------------
// K5: out[t,:] = sum_{m<128} attn[t,m] * values[vidx[t,m], :]
// ---------------------------------------------------------------------------
__global__ __launch_bounds__(128) void k5_out(const float* __restrict__ values,
                                              float* __restrict__ out)
{
    __shared__ float sa[128];
    __shared__ int   sv[128];
    const int t = blockIdx.x;
    const int tid = threadIdx.x;
    sa[tid] = g_attn[(size_t)t * 128 + tid];
    sv[tid] = g_vidx[(size_t)t * 128 + tid];
    __syncthreads();

    const float4* V = (const float4*)values;
    float4 acc = make_float4(0.f, 0.f, 0.f, 0.f);
#pragma unroll 8
    for (int m = 0; m < 128; m++) {
        float a = sa[m];
        float4 vv = V[(size_t)sv[m] * 128 + tid];
        acc.x = fmaf(a, vv.x, acc.x);
        acc.y = fmaf(a, vv.y, acc.y);
        acc.z = fmaf(a, vv.z, acc.z);
        acc.w = fmaf(a, vv.w, acc.w);
    }
    ((float4*)out)[(size_t)t * 128 + tid] = acc;
}

// ---------------------------------------------------------------------------
extern "C" void kernel_launch(void* const* d_in, const int* in_sizes, int n_in,
                              void* d_out, int out_size)
{
    const float* x      = (const float*)d_in[0];  // (4,1024,512)
    const float* Wq     = (const float*)d_in[1];  // (2048,512)
    const float* ln_g   = (const float*)d_in[2];  // (128,)
    const float* ln_b   = (const float*)d_in[3];  // (128,)
    const float* keys   = (const float*)d_in[4];  // (8,256,2,128)
    const float* values = (const float*)d_in[5];  // (65536,512)
    float* out = (float*)d_out;                   // (4,1024,512)

    k1_gemm<<<dim3(NTOKS / 128, QDV / 128), 256>>>(x, Wq);
    k2_ln<<<(NTOKS * 16) / 8, 256>>>(ln_g, ln_b);
    k3_fused<<<dim3(NTOKS / 32, HV), 256>>>(keys);
    k5_out<<<NTOKS, 128>>>(values, out);
}